// round 15
// baseline (speedup 1.0000x reference)
#include <cuda_runtime.h>

// Persistent scratch (no allocations allowed). Reset by the spinner block at
// the end of each launch so every graph replay sees clean state.
__device__ float    g_sum    = 0.f;
__device__ unsigned g_ticket = 0u;

__device__ __forceinline__ float leaky(float v) {
    return v >= 0.f ? v : 0.2f * v;
}

// Cold path: full edge contribution (only ~E/N ~ 32 executions chip-wide).
// __noinline__ keeps the hot scan loop lean.
__device__ __noinline__ void contribute(int i, int dst,
                                        const float* __restrict__ h,
                                        const float* __restrict__ W,
                                        const float* __restrict__ bptr,
                                        int D) {
    const float4* __restrict__ ra = (const float4*)(h + (size_t)i * D);
    const float4* __restrict__ wa = (const float4*)W;
    const float4* __restrict__ rb = (const float4*)(h + (size_t)dst * D);
    const float4* __restrict__ wb = (const float4*)(W + D);
    float sa = 0.f, sb = 0.f;
    int n4 = D >> 2;
    #pragma unroll 8
    for (int k = 0; k < n4; k++) {
        float4 x = ra[k], y = wa[k];
        sa += x.x * y.x + x.y * y.y + x.z * y.z + x.w * y.w;
        float4 u = rb[k], v = wb[k];
        sb += u.x * v.x + u.y * v.y + u.z * v.z + u.w * v.w;
    }
    atomicAdd(&g_sum, leaky(sa + sb + __ldg(bptr)));
}

// ---------------------------------------------------------------------------
// Single kernel, single resident wave:
//   block 0          : spinner — computes s_src[i], s_dst[j] DURING the scan,
//                      spin-waits on the ticket, then divide+store (tiny tail)
//   blocks 1..nB-1   : lean grid-stride scan; matches fold into g_sum
// ---------------------------------------------------------------------------
__global__ void __launch_bounds__(256, 8)
gat_one(const int4* __restrict__ g4, unsigned nPairs, int rem,
        const int2* __restrict__ gall,
        const float* __restrict__ h, const float* __restrict__ W,
        const float* __restrict__ bptr,
        const int* __restrict__ ip, const int* __restrict__ jp,
        int D, float* __restrict__ out) {
    const int t = threadIdx.x;
    const int i = __ldg(ip);
    const bool multi  = gridDim.x > 1u;
    const bool isSpin = multi && (blockIdx.x == 0u);

    if (!isSpin) {
        // ---- scan path ----
        const unsigned nWork  = multi ? gridDim.x - 1u : 1u;
        const unsigned worker = multi ? blockIdx.x - 1u : 0u;
        const unsigned stride = nWork * 256u;
        for (unsigned u = worker * 256u + t; u < nPairs; u += stride) {
            int4 p = __ldg(&g4[u]);
            if (__builtin_expect(p.x == i, 0)) contribute(i, p.y, h, W, bptr, D);
            if (__builtin_expect(p.z == i, 0)) contribute(i, p.w, h, W, bptr, D);
        }
        if (rem && worker == 0 && t == 0) {
            int2 p = __ldg(&gall[(size_t)2 * nPairs]);   // trailing odd edge
            if (p.x == i) contribute(i, p.y, h, W, bptr, D);
        }
        __threadfence();   // release: g_sum contributions visible before ticket
        __syncthreads();
        if (t == 0) atomicAdd(&g_ticket, 1u);
        if (multi) return;
        // grid == 1: fall through, this block is also the finisher
    }

    // ---- spinner / finisher block ----
    const int lane = t & 31;
    const int wid  = t >> 5;
    __shared__ float sh[2];

    if (wid < 2) {   // overlapped with the scan: both scalar dots
        const int row = (wid == 0) ? i : __ldg(jp);
        const float* __restrict__ wv = (wid == 0) ? W : (W + D);
        float s = 0.f;
        for (int k = 4 * lane; k < D; k += 128) {
            float4 a = *(const float4*)(h + (size_t)row * D + k);
            float4 b = *(const float4*)(wv + k);
            s += a.x * b.x + a.y * b.y + a.z * b.z + a.w * b.w;
        }
        #pragma unroll
        for (int off = 16; off > 0; off >>= 1)
            s += __shfl_down_sync(0xffffffffu, s, off);
        if (lane == 0) sh[wid] = s;
    }
    __syncthreads();

    if (t == 0) {
        const unsigned target = multi ? gridDim.x - 1u : 1u;
        while (*(volatile unsigned*)&g_ticket < target) __nanosleep(64);
        __threadfence();   // acquire: see all g_sum contributions
        float sum = *(volatile float*)&g_sum;
        float e = leaky(sh[0] + sh[1] + __ldg(bptr));
        out[0] = e / sum;
        // reset persistent state for the next graph replay
        g_sum = 0.f;
        __threadfence();
        g_ticket = 0u;
    }
}

extern "C" void kernel_launch(void* const* d_in, const int* in_sizes, int n_in,
                              void* d_out, int out_size) {
    // metadata order: g (E*2 int32), h (N*D f32), i, j, W (2D f32), b (1 f32)
    const int*   g  = (const int*)d_in[0];
    const float* h  = (const float*)d_in[1];
    const int*   ip = (const int*)d_in[2];
    const int*   jp = (const int*)d_in[3];
    const float* W  = (const float*)d_in[4];
    const float* b  = (const float*)d_in[5];
    float* out = (float*)d_out;

    long long E = (long long)in_sizes[0] / 2;
    int D = in_sizes[4] / 2;

    unsigned nPairs = (unsigned)(E / 2);   // int4 units (2 edges each)
    int rem = (int)(E & 1);

    // Single resident wave (148 SMs x 8 blocks of 256): spinner block 0 plus
    // scan workers, all co-resident -> spin-wait cannot deadlock.
    unsigned nBlocks = 148u * 8u;
    unsigned needed  = (nPairs + 255u) / 256u + 1u;   // +1 for the spinner
    if (needed < nBlocks) nBlocks = needed;
    if (nBlocks < 1u) nBlocks = 1u;

    gat_one<<<nBlocks, 256>>>((const int4*)g, nPairs, rem, (const int2*)g,
                              h, W, b, ip, jp, D, out);
}

// round 16
// speedup vs baseline: 1.1622x; 1.1622x over previous
#include <cuda_runtime.h>

// Persistent scratch (no allocations allowed). g_cnt reset by finish kernel.
#define MAX_MATCH 8192
__device__ int   g_cnt = 0;
__device__ float g_ssrc, g_sdstj;
__device__ int   g_dsts[MAX_MATCH];

__device__ __forceinline__ float leaky(float v) {
    return v >= 0.f ? v : 0.2f * v;
}

// ---------------------------------------------------------------------------
// Kernel 1: lean scan (unchanged R4 hot loop) + one extra block that computes
// the two scalar dots concurrently with the scan.
// ---------------------------------------------------------------------------
__global__ void __launch_bounds__(256)
gat_scan(const int4* __restrict__ g4, unsigned nPairs, int rem,
         const int2* __restrict__ gall,
         const float* __restrict__ h, const float* __restrict__ W,
         const int* __restrict__ ip, const int* __restrict__ jp, int D) {
    const unsigned t = threadIdx.x;

    if (blockIdx.x == gridDim.x - 1u) {
        // ---- scalars block: warp 0 -> s_src[i], warp 1 -> s_dst[j] ----
        const int lane = t & 31;
        const int wid  = t >> 5;
        if (wid < 2) {
            const int row = (wid == 0) ? __ldg(ip) : __ldg(jp);
            const float* __restrict__ wv = (wid == 0) ? W : (W + D);
            float s = 0.f;
            for (int k = 4 * lane; k < D; k += 128) {
                float4 a = *(const float4*)(h + (size_t)row * D + k);
                float4 b = *(const float4*)(wv + k);
                s += a.x * b.x + a.y * b.y + a.z * b.z + a.w * b.w;
            }
            #pragma unroll
            for (int off = 16; off > 0; off >>= 1)
                s += __shfl_down_sync(0xffffffffu, s, off);
            if (lane == 0) {
                if (wid == 0) g_ssrc = s; else g_sdstj = s;
            }
        }
        return;
    }

    // ---- scan blocks: 2 x int4 (4 edges) per thread, coalesced ----
    const unsigned base = blockIdx.x * 512u + t;
    const int i = __ldg(ip);

    int4 p0, p1;
    const bool v0 = base < nPairs;
    const bool v1 = (base + 256u) < nPairs;
    if (v0) p0 = __ldg(&g4[base]);
    if (v1) p1 = __ldg(&g4[base + 256u]);

    if (v0) {
        if (p0.x == i) { int k = atomicAdd(&g_cnt, 1); if (k < MAX_MATCH) g_dsts[k] = p0.y; }
        if (p0.z == i) { int k = atomicAdd(&g_cnt, 1); if (k < MAX_MATCH) g_dsts[k] = p0.w; }
    }
    if (v1) {
        if (p1.x == i) { int k = atomicAdd(&g_cnt, 1); if (k < MAX_MATCH) g_dsts[k] = p1.y; }
        if (p1.z == i) { int k = atomicAdd(&g_cnt, 1); if (k < MAX_MATCH) g_dsts[k] = p1.w; }
    }
    if (rem && blockIdx.x == 0 && t == 0) {
        int2 p = __ldg(&gall[(size_t)2 * nPairs]);   // trailing odd edge
        if (p.x == i) { int k = atomicAdd(&g_cnt, 1); if (k < MAX_MATCH) g_dsts[k] = p.y; }
    }
}

// ---------------------------------------------------------------------------
// Kernel 2: finish, one flat latency chain. 1024 threads, thread-per-entry.
// ---------------------------------------------------------------------------
__global__ void __launch_bounds__(1024)
gat_finish(const float* __restrict__ h, const float* __restrict__ W,
           const float* __restrict__ bptr, int D, float* __restrict__ out) {
    const int t = threadIdx.x;
    const int lane = t & 31;
    const int w = t >> 5;               // 0..31

    int cnt = g_cnt;                    // hop 1
    if (cnt > MAX_MATCH) cnt = MAX_MATCH;

    const float ssrc = g_ssrc;          // written by scan's scalars block
    const float bval = __ldg(bptr);

    __shared__ float sh_warp[32];

    float v = 0.f;
    if (t < cnt) {
        int dst = g_dsts[t];            // hop 2
        const float4* __restrict__ a = (const float4*)(h + (size_t)dst * D);
        const float4* __restrict__ b = (const float4*)(W + D);
        float acc = 0.f;
        int n4 = D >> 2;
        #pragma unroll 8
        for (int k = 0; k < n4; k++) {  // hop 3: 32 independent float4 loads
            float4 x = a[k];
            float4 y = b[k];
            acc += x.x * y.x + x.y * y.y + x.z * y.z + x.w * y.w;
        }
        v = leaky(ssrc + acc + bval);
    }
    // rare overflow: entries beyond 1024
    for (int m = 1024 + t; m < cnt; m += 1024) {
        int dst = g_dsts[m];
        const float4* __restrict__ a = (const float4*)(h + (size_t)dst * D);
        const float4* __restrict__ b = (const float4*)(W + D);
        float acc = 0.f;
        int n4 = D >> 2;
        for (int k = 0; k < n4; k++) {
            float4 x = a[k];
            float4 y = b[k];
            acc += x.x * y.x + x.y * y.y + x.z * y.z + x.w * y.w;
        }
        v += leaky(ssrc + acc + bval);
    }

    // block reduction
    #pragma unroll
    for (int off = 16; off > 0; off >>= 1)
        v += __shfl_down_sync(0xffffffffu, v, off);
    if (lane == 0) sh_warp[w] = v;
    __syncthreads();

    if (t == 0) {
        float sum = 0.f;
        #pragma unroll
        for (int k = 0; k < 32; k++) sum += sh_warp[k];
        float e = leaky(ssrc + g_sdstj + bval);
        out[0] = e / sum;
        g_cnt = 0;   // reset for next graph replay
    }
}

extern "C" void kernel_launch(void* const* d_in, const int* in_sizes, int n_in,
                              void* d_out, int out_size) {
    // metadata order: g (E*2 int32), h (N*D f32), i, j, W (2D f32), b (1 f32)
    const int*   g  = (const int*)d_in[0];
    const float* h  = (const float*)d_in[1];
    const int*   ip = (const int*)d_in[2];
    const int*   jp = (const int*)d_in[3];
    const float* W  = (const float*)d_in[4];
    const float* b  = (const float*)d_in[5];
    float* out = (float*)d_out;

    long long E = (long long)in_sizes[0] / 2;
    int D = in_sizes[4] / 2;

    unsigned nPairs = (unsigned)(E / 2);   // int4 units (2 edges each)
    int rem = (int)(E & 1);

    unsigned scanBlocks = (nPairs + 511u) / 512u;
    if (scanBlocks < 1u) scanBlocks = 1u;

    gat_scan<<<scanBlocks + 1u, 256>>>((const int4*)g, nPairs, rem,
                                       (const int2*)g, h, W, ip, jp, D);
    gat_finish<<<1, 1024>>>(h, W, b, D, out);
}

// round 17
// speedup vs baseline: 1.5203x; 1.3081x over previous
#include <cuda_runtime.h>

// Persistent scratch (no allocations allowed). g_cnt reset by finish kernel.
#define MAX_MATCH 8192
__device__ int g_cnt = 0;
__device__ int g_dsts[MAX_MATCH];

__device__ __forceinline__ float leaky(float v) {
    return v >= 0.f ? v : 0.2f * v;
}

// ---------------------------------------------------------------------------
// Kernel 1: lean scan (R4 hot loop). Triggers the dependent launch at entry
// so gat_finish's launch + prelude overlap the scan.
// ---------------------------------------------------------------------------
__global__ void __launch_bounds__(256)
gat_scan(const int4* __restrict__ g4, unsigned nPairs, int rem,
         const int2* __restrict__ gall, const int* __restrict__ ip) {
    cudaTriggerProgrammaticLaunchCompletion();

    const unsigned t = threadIdx.x;
    const unsigned base = blockIdx.x * 512u + t;
    const int i = __ldg(ip);

    int4 p0, p1;
    const bool v0 = base < nPairs;
    const bool v1 = (base + 256u) < nPairs;
    if (v0) p0 = __ldg(&g4[base]);
    if (v1) p1 = __ldg(&g4[base + 256u]);

    if (v0) {
        if (p0.x == i) { int k = atomicAdd(&g_cnt, 1); if (k < MAX_MATCH) g_dsts[k] = p0.y; }
        if (p0.z == i) { int k = atomicAdd(&g_cnt, 1); if (k < MAX_MATCH) g_dsts[k] = p0.w; }
    }
    if (v1) {
        if (p1.x == i) { int k = atomicAdd(&g_cnt, 1); if (k < MAX_MATCH) g_dsts[k] = p1.y; }
        if (p1.z == i) { int k = atomicAdd(&g_cnt, 1); if (k < MAX_MATCH) g_dsts[k] = p1.w; }
    }
    if (rem && blockIdx.x == 0 && t == 0) {
        int2 p = __ldg(&gall[(size_t)2 * nPairs]);   // trailing odd edge
        if (p.x == i) { int k = atomicAdd(&g_cnt, 1); if (k < MAX_MATCH) g_dsts[k] = p.y; }
    }
}

// Warp-collective dot, coalesced: lane reads float4 at 4*lane (D=128 covered).
__device__ __forceinline__ float warp_dot(const float* __restrict__ row,
                                          const float* __restrict__ wvec,
                                          int D, int lane) {
    float s = 0.f;
    for (int k = 4 * lane; k < D; k += 128) {
        float4 a = *(const float4*)(row + k);
        float4 b = *(const float4*)(wvec + k);
        s += a.x * b.x + a.y * b.y + a.z * b.z + a.w * b.w;
    }
    #pragma unroll
    for (int off = 16; off > 0; off >>= 1)
        s += __shfl_down_sync(0xffffffffu, s, off);
    return s;   // valid on lane 0
}

// ---------------------------------------------------------------------------
// Kernel 2: finish with PDL overlap. 1024 threads (32 warps).
//   prelude (overlapped with scan): s_src[i], s_dst[j]
//   after grid-dependency sync: warp-per-entry dots (R4 shape), reduce, write.
// ---------------------------------------------------------------------------
__global__ void __launch_bounds__(1024)
gat_finish(const float* __restrict__ h, const float* __restrict__ W,
           const float* __restrict__ bptr,
           const int* __restrict__ ip, const int* __restrict__ jp,
           int D, float* __restrict__ out) {
    const int t = threadIdx.x;
    const int lane = t & 31;
    const int w = t >> 5;                 // 0..31

    __shared__ float sh_ssrc, sh_sdstj, sh_s[64], sh_warp[32];

    // ---- prelude: independent of the scan, overlaps it under PDL ----
    const float bval = __ldg(bptr);
    const int i = __ldg(ip);
    if (w == 0) {
        float s = warp_dot(h + (size_t)i * D, W, D, lane);
        if (lane == 0) sh_ssrc = s;
    } else if (w == 1) {
        float s = warp_dot(h + (size_t)__ldg(jp) * D, W + D, D, lane);
        if (lane == 0) sh_sdstj = s;
    }

    // ---- wait for the scan grid to complete (HW-managed, no atomics) ----
    cudaGridDependencySynchronize();

    int cnt = g_cnt;
    if (cnt > MAX_MATCH) cnt = MAX_MATCH;

    // ---- warp-per-entry: warp w handles entries w and w+32 ----
    float s0 = 0.f, s1 = 0.f;
    if (w < cnt)
        s0 = warp_dot(h + (size_t)g_dsts[w] * D, W + D, D, lane);
    if (w + 32 < cnt)
        s1 = warp_dot(h + (size_t)g_dsts[w + 32] * D, W + D, D, lane);
    if (lane == 0) { sh_s[w] = s0; sh_s[w + 32] = s1; }
    __syncthreads();

    const float ssrc = sh_ssrc;

    // leaky+sum over first min(cnt,64) via 2 warps; rare overflow via all warps
    float v = 0.f;
    if (w < 2) {
        int top = cnt < 64 ? cnt : 64;
        v = (t < top) ? leaky(ssrc + sh_s[t] + bval) : 0.f;
    }
    for (int m = 64 + w; m < cnt; m += 32) {
        float s = warp_dot(h + (size_t)g_dsts[m] * D, W + D, D, lane);
        if (lane == 0) v += leaky(ssrc + s + bval);
    }

    #pragma unroll
    for (int off = 16; off > 0; off >>= 1)
        v += __shfl_down_sync(0xffffffffu, v, off);
    if (lane == 0) sh_warp[w] = v;
    __syncthreads();

    if (t == 0) {
        float sum = 0.f;
        #pragma unroll
        for (int k = 0; k < 32; k++) sum += sh_warp[k];
        float e = leaky(ssrc + sh_sdstj + bval);
        out[0] = e / sum;
        g_cnt = 0;   // reset for next graph replay
    }
}

extern "C" void kernel_launch(void* const* d_in, const int* in_sizes, int n_in,
                              void* d_out, int out_size) {
    // metadata order: g (E*2 int32), h (N*D f32), i, j, W (2D f32), b (1 f32)
    const int*   g  = (const int*)d_in[0];
    const float* h  = (const float*)d_in[1];
    const int*   ip = (const int*)d_in[2];
    const int*   jp = (const int*)d_in[3];
    const float* W  = (const float*)d_in[4];
    const float* b  = (const float*)d_in[5];
    float* out = (float*)d_out;

    long long E = (long long)in_sizes[0] / 2;
    int D = in_sizes[4] / 2;

    unsigned nPairs = (unsigned)(E / 2);   // int4 units (2 edges each)
    int rem = (int)(E & 1);

    unsigned scanBlocks = (nPairs + 511u) / 512u;
    if (scanBlocks < 1u) scanBlocks = 1u;

    gat_scan<<<scanBlocks, 256>>>((const int4*)g, nPairs, rem,
                                  (const int2*)g, ip);

    // Dependent launch with programmatic stream serialization: gat_finish's
    // launch + prelude overlap the scan; cudaGridDependencySynchronize() in
    // the kernel provides the ordering guarantee.
    cudaLaunchConfig_t cfg = {};
    cfg.gridDim  = dim3(1, 1, 1);
    cfg.blockDim = dim3(1024, 1, 1);
    cfg.dynamicSmemBytes = 0;
    cfg.stream = 0;   // legacy default stream (same as <<<>>> above)
    cudaLaunchAttribute attrs[1];
    attrs[0].id = cudaLaunchAttributeProgrammaticStreamSerialization;
    attrs[0].val.programmaticStreamSerializationAllowed = 1;
    cfg.attrs = attrs;
    cfg.numAttrs = 1;
    cudaLaunchKernelEx(&cfg, gat_finish, h, W, b, ip, jp, D, out);
}